// round 11
// baseline (speedup 1.0000x reference)
#include <cuda_runtime.h>
#include <cuda_bf16.h>
#include <cstdint>

#define SEQ   256
#define XDIM  120
#define H     400
#define ZROWS 3200
#define M     200
#define TROWS 257
#define N_ARC  65536
#define N_SIB  200000
#define N_GP   200000
#define N_GSIB 300000
#define NTOT  (N_ARC + N_SIB + N_GP + N_GSIB)
#define NCLUST 16          // CTAs per direction (one cluster each)
#define UPC    25          // hidden units per CTA (400/16)
#define MC    50           // m-chunk size (4 chunks x 50 = M)
#define TABSZ (TROWS * MC)

// ---------------- static device scratch (no allocations) ----------------
__device__ float g_x[SEQ * XDIM];        // embedded inputs [s][120]
__device__ float g_z[SEQ * ZROWS];       // z_in both dirs [s][dir*1600 + gate*400 + u]
__device__ float g_states[SEQ * 800];    // [s][ hf(400) | hb(400) ]
__device__ float g_ptab[12 * TROWS * M]; // 12 projection tables, row 256 = null_sib for tabs 7,10

// ---------------- helpers ----------------
__device__ __forceinline__ float fast_tanh(float x) {
    return 1.0f - 2.0f / (__expf(2.0f * x) + 1.0f);
}
__device__ __forceinline__ float tanh_ap(float x) {
    float y; asm("tanh.approx.f32 %0, %1;" : "=f"(y) : "f"(x)); return y;
}
__device__ __forceinline__ float fast_sigmoid(float x) {
    return 1.0f / (1.0f + __expf(-x));
}
__device__ __forceinline__ void cluster_sync_() {
    asm volatile("barrier.cluster.arrive.aligned;" ::: "memory");
    asm volatile("barrier.cluster.wait.aligned;" ::: "memory");
}
__device__ __forceinline__ uint32_t ctarank_() {
    uint32_t r; asm("mov.u32 %0, %%cluster_ctarank;" : "=r"(r)); return r;
}
__device__ __forceinline__ uint32_t smem_u32(const void* p) {
    uint32_t a;
    asm("{ .reg .u64 t; cvta.to.shared.u64 t, %1; cvt.u32.u64 %0, t; }" : "=r"(a) : "l"(p));
    return a;
}
__device__ __forceinline__ void st_dsmem_f32(uint32_t local_addr, uint32_t rank, float v) {
    uint32_t remote;
    asm volatile("mapa.shared::cluster.u32 %0, %1, %2;" : "=r"(remote) : "r"(local_addr), "r"(rank));
    asm volatile("st.shared::cluster.f32 [%0], %1;" :: "r"(remote), "f"(v) : "memory");
}

// ---------------- 0. prep: write null_sib rows ----------------
__global__ void prep_kernel(const float* __restrict__ null_sib) {
    int t = threadIdx.x;
    if (t < M) {
        float v = null_sib[t];
        g_ptab[(7 * TROWS + 256) * M + t]  = v;
        g_ptab[(10 * TROWS + 256) * M + t] = v;
    }
}

// ---------------- 0b. zero the output (scores accumulate via atomicAdd) ----------------
__global__ void zero_out_kernel(float* __restrict__ out) {
    int i = blockIdx.x * 1024 + threadIdx.x;
    if (i < NTOT) out[i] = 0.0f;
}

// ---------------- 1. embedding concat ----------------
__global__ void embed_kernel(const int* __restrict__ words, const int* __restrict__ tags,
                             const float* __restrict__ wemb, const float* __restrict__ temb) {
    int s = blockIdx.x, j = threadIdx.x;
    if (j < XDIM) {
        float v = (j < 100) ? wemb[words[s] * 100 + j] : temb[tags[s] * 20 + (j - 100)];
        g_x[s * XDIM + j] = v;
    }
}

// ---------------- 2. z_in = Wih @ x + b, both directions (3200 rows x 256 s) ----------------
__global__ __launch_bounds__(256) void zin_kernel(
    const float* __restrict__ Wf, const float* __restrict__ bf,
    const float* __restrict__ Wb, const float* __restrict__ bb) {
    __shared__ float Ws[64][121];
    __shared__ float Xs[32][121];
    int r0 = blockIdx.x * 64;
    int s0 = blockIdx.y * 32;
    int tid = threadIdx.x;

    for (int idx = tid; idx < 64 * 120; idx += 256) {
        int rl = idx / 120, k = idx % 120;
        int r = r0 + rl;
        Ws[rl][k] = (r < 1600) ? Wf[r * 120 + k] : Wb[(r - 1600) * 120 + k];
    }
    for (int idx = tid; idx < 32 * 120; idx += 256) {
        int sl = idx / 120, k = idx % 120;
        Xs[sl][k] = g_x[(s0 + sl) * XDIM + k];
    }
    __syncthreads();

    int tx = tid & 15;   // -> 2 sequence positions
    int ty = tid >> 4;   // -> 4 rows
    float acc[4][2] = {};
    for (int k = 0; k < 120; ++k) {
        float x0 = Xs[tx * 2 + 0][k];
        float x1 = Xs[tx * 2 + 1][k];
#pragma unroll
        for (int i = 0; i < 4; ++i) {
            float w = Ws[ty * 4 + i][k];
            acc[i][0] += w * x0;
            acc[i][1] += w * x1;
        }
    }
#pragma unroll
    for (int i = 0; i < 4; ++i) {
        int r = r0 + ty * 4 + i;
        float bias = (r < 1600) ? bf[r] : bb[r - 1600];
#pragma unroll
        for (int j = 0; j < 2; ++j) {
            int s = s0 + tx * 2 + j;
            g_z[s * ZROWS + r] = acc[i][j] + bias;
        }
    }
}

// ---------------- 3. cluster biLSTM: 2 clusters of 16 CTAs, DSMEM h-exchange ----------------
// (identical to R8's passing version: cluster.sync per step, float4 matvec)
__global__ __launch_bounds__(256, 1) void lstm_kernel(
    const float* __restrict__ Whh_f, const float* __restrict__ Whh_b) {
    const int dir  = blockIdx.x >> 4;       // blocks 0-15: fwd cluster, 16-31: bwd cluster
    const uint32_t rank = ctarank_();       // 0..15
    const int u0   = (int)rank * UPC;       // first hidden unit of this CTA
    const float* Whh = dir ? Whh_b : Whh_f;

    const int tid   = threadIdx.x;
    const int chunk = tid & 1;              // 2 col chunks of 200
    const int rl    = tid >> 1;             // 0..127 local rows; valid < 100
    const bool valid = rl < 100;
    const int gate  = valid ? (rl / UPC) : 0;
    const int lu    = valid ? (rl % UPC) : 0;
    const int grow  = gate * 400 + u0 + lu;

    // preload Whh slice: 200 cols per thread = 50 float4 = 200 regs
    float4 w[50];
    {
        const float4* wp = (const float4*)(Whh + grow * 400 + chunk * 200);
#pragma unroll
        for (int j = 0; j < 50; ++j) w[j] = wp[j];
    }

    __shared__ __align__(16) float hs[2][400];
    __shared__ float zs[100];
    float c = 0.0f;  // cell state (threads 0..24)

    // init read buffer for step 0
    for (int i = tid; i < 400; i += 256) hs[0][i] = 0.0f;
    __syncthreads();

    const uint32_t hs_base = smem_u32(&hs[0][0]);

    for (int step = 0; step < SEQ; ++step) {
        const int s = dir ? (SEQ - 1 - step) : step;
        const int p = step & 1;

        // prefetch z_in (independent of h; overlaps matvec)
        float zp0, zp1, zp2, zp3;
        if (tid < UPC) {
            const float* zin = g_z + s * ZROWS + dir * 1600 + u0 + tid;
            zp0 = __ldg(zin);
            zp1 = __ldg(zin + 400);
            zp2 = __ldg(zin + 800);
            zp3 = __ldg(zin + 1200);
        }

        // matvec: row rl (gate,lu), cols chunk*200..+200 from hs[p]
        const float4* hv = (const float4*)(&hs[p][chunk * 200]);
        float ax = 0.f, ay = 0.f, az = 0.f, aw = 0.f;
#pragma unroll
        for (int j = 0; j < 50; ++j) {
            float4 v = hv[j];
            ax += w[j].x * v.x;
            ay += w[j].y * v.y;
            az += w[j].z * v.z;
            aw += w[j].w * v.w;
        }
        float val = (ax + ay) + (az + aw);
        val += __shfl_xor_sync(0xFFFFFFFFu, val, 1);   // combine the 2 col chunks
        if (chunk == 0 && valid) zs[rl] = val;
        __syncthreads();

        if (tid < UPC) {
            float zi = zs[0 * UPC + tid] + zp0;
            float zf = zs[1 * UPC + tid] + zp1;
            float zg = zs[2 * UPC + tid] + zp2;
            float zo = zs[3 * UPC + tid] + zp3;
            float iv = fast_sigmoid(zi);
            float fv = fast_sigmoid(zf);
            float gv = fast_tanh(zg);
            float ov = fast_sigmoid(zo);
            c = fv * c + iv * gv;
            float h = ov * fast_tanh(c);
            // persist for downstream projections
            __stcg(g_states + s * 800 + dir * 400 + u0 + tid, h);
            // push into hs[p^1][u0+tid] of every CTA in the cluster (incl. self)
            uint32_t dst = hs_base + (uint32_t)((p ^ 1) * 400 + u0 + tid) * 4u;
#pragma unroll
            for (uint32_t r = 0; r < NCLUST; ++r) st_dsmem_f32(dst, r, h);
        }
        cluster_sync_();   // release our DSMEM stores, acquire peers'
    }
}

// ---------------- 4. 12 projections: ptab[p][s][m] = sum_d W_proj[p][m][d]*states[s][d] ----------------
__global__ __launch_bounds__(224) void proj_kernel(const float* __restrict__ W_proj) {
    extern __shared__ float sm[];
    float* ws = sm;            // [100 k][200 m]
    float* st = sm + 20000;    // [16 s][100 k]

    const int p   = blockIdx.x;
    const int s0  = blockIdx.y * 16;
    const int tid = threadIdx.x;

    float acc[16];
#pragma unroll
    for (int i = 0; i < 16; ++i) acc[i] = 0.0f;

    for (int dc = 0; dc < 8; ++dc) {
        __syncthreads();
        for (int idx = tid; idx < 20000; idx += 224) {
            int m = idx / 100, k = idx % 100;
            ws[k * 200 + m] = W_proj[(p * 200 + m) * 800 + dc * 100 + k];
        }
        for (int idx = tid; idx < 1600; idx += 224) {
            int sl = idx / 100, k = idx % 100;
            st[sl * 100 + k] = g_states[(s0 + sl) * 800 + dc * 100 + k];
        }
        __syncthreads();

        if (tid < 200) {
            for (int k = 0; k < 100; k += 4) {
                float w0 = ws[(k + 0) * 200 + tid];
                float w1 = ws[(k + 1) * 200 + tid];
                float w2 = ws[(k + 2) * 200 + tid];
                float w3 = ws[(k + 3) * 200 + tid];
#pragma unroll
                for (int sl = 0; sl < 16; ++sl) {
                    float4 v = *(const float4*)(st + sl * 100 + k);
                    acc[sl] += w0 * v.x + w1 * v.y + w2 * v.z + w3 * v.w;
                }
            }
        }
    }
    if (tid < 200) {
#pragma unroll
        for (int sl = 0; sl < 16; ++sl)
            g_ptab[(p * TROWS + s0 + sl) * M + tid] = acc[sl];
    }
}

// ---------------- 5. scoring: smem-resident tables, m-chunked, warp per score ----------------
// Block = (index slice via grid.x, m-chunk via grid.y) for one score type.
// All NTAB tables (257 rows x 50 m) live in smem; warp gathers rows conflict-free
// (lane = m), computes partial dot tanh(sum_rows)*W over its chunk, atomicAdds to out.
template <int NTAB, int T0, int T1, int T2, int T3, int WROW>
__global__ __launch_bounds__(1024) void score_smem_kernel(
    const int* __restrict__ i0, const int* __restrict__ i1,
    const int* __restrict__ i2, const int* __restrict__ i3,
    const float* __restrict__ W_score, float* __restrict__ out,
    int N, int out_off) {
    extern __shared__ float ts[];  // [NTAB][TROWS][MC]
    const int chunk = blockIdx.y;
    const int tid   = threadIdx.x;
    const int lane  = tid & 31;

    // load tables for this chunk
    const int tabid[4] = {T0, T1, T2, T3};
#pragma unroll
    for (int t = 0; t < NTAB; ++t) {
        const float* src = g_ptab + (size_t)tabid[t] * TROWS * M + chunk * MC;
        float* dst = ts + t * TABSZ;
        for (int idx = tid; idx < TABSZ; idx += 1024) {
            int r = idx / MC, m = idx - r * MC;
            dst[idx] = src[r * M + m];
        }
    }
    // W slice for this chunk: lane -> m=lane, m=lane+32 (valid < 50)
    float w1 = W_score[WROW * M + chunk * MC + lane];
    float w2 = (lane < MC - 32) ? W_score[WROW * M + chunk * MC + 32 + lane] : 0.0f;
    __syncthreads();

    const int warp   = (blockIdx.x * 1024 + tid) >> 5;
    const int nwarps = gridDim.x * 32;
    for (int i = warp; i < N; i += nwarps) {
        int a = __ldg(i0 + i);
        int b = __ldg(i1 + i);
        const float* r0 = ts + a * MC;
        const float* r1 = ts + TABSZ + b * MC;
        float s1 = r0[lane] + r1[lane];
        float s2 = (lane < MC - 32) ? (r0[lane + 32] + r1[lane + 32]) : 0.0f;
        if (NTAB > 2) {
            int cc = __ldg(i2 + i);
            const float* r2 = ts + 2 * TABSZ + cc * MC;
            s1 += r2[lane];
            if (lane < MC - 32) s2 += r2[lane + 32];
        }
        if (NTAB > 3) {
            int dd = __ldg(i3 + i);
            const float* r3 = ts + 3 * TABSZ + dd * MC;
            s1 += r3[lane];
            if (lane < MC - 32) s2 += r3[lane + 32];
        }
        float v = tanh_ap(s1) * w1;
        if (lane < MC - 32) v += tanh_ap(s2) * w2;
        v += __shfl_xor_sync(0xFFFFFFFFu, v, 16);
        v += __shfl_xor_sync(0xFFFFFFFFu, v, 8);
        v += __shfl_xor_sync(0xFFFFFFFFu, v, 4);
        v += __shfl_xor_sync(0xFFFFFFFFu, v, 2);
        v += __shfl_xor_sync(0xFFFFFFFFu, v, 1);
        if (lane == 0) atomicAdd(out + out_off + i, v);
    }
}

// ---------------- launch ----------------
extern "C" void kernel_launch(void* const* d_in, const int* in_sizes, int n_in,
                              void* d_out, int out_size) {
    const int*   words      = (const int*)d_in[0];
    const int*   tags       = (const int*)d_in[1];
    const int*   arc_head   = (const int*)d_in[2];
    const int*   arc_mod    = (const int*)d_in[3];
    const int*   sib_head   = (const int*)d_in[4];
    const int*   sib_mod    = (const int*)d_in[5];
    const int*   sib_sib    = (const int*)d_in[6];
    const int*   gp_head    = (const int*)d_in[7];
    const int*   gp_mod     = (const int*)d_in[8];
    const int*   gp_grand   = (const int*)d_in[9];
    const int*   gsib_head  = (const int*)d_in[10];
    const int*   gsib_mod   = (const int*)d_in[11];
    const int*   gsib_sib   = (const int*)d_in[12];
    const int*   gsib_grand = (const int*)d_in[13];
    const float* word_emb   = (const float*)d_in[14];
    const float* tag_emb    = (const float*)d_in[15];
    const float* Wih_f      = (const float*)d_in[16];
    const float* Whh_f      = (const float*)d_in[17];
    const float* b_f        = (const float*)d_in[18];
    const float* Wih_b      = (const float*)d_in[19];
    const float* Whh_b      = (const float*)d_in[20];
    const float* b_b        = (const float*)d_in[21];
    const float* W_proj     = (const float*)d_in[22];
    const float* W_score    = (const float*)d_in[23];
    const float* null_sib   = (const float*)d_in[24];
    float* out = (float*)d_out;

    // arc: tabs 0,1 | sib: 5,6,7 | gp: 3,4,2 | gsib: 8,9,10,11
    auto karc  = score_smem_kernel<2, 0, 1, 0, 0, 0>;
    auto ksib  = score_smem_kernel<3, 5, 6, 7, 0, 1>;
    auto kgp   = score_smem_kernel<3, 3, 4, 2, 0, 2>;
    auto kgsib = score_smem_kernel<4, 8, 9, 10, 11, 3>;

    static bool attr_done = false;
    if (!attr_done) {
        cudaFuncSetAttribute(proj_kernel, cudaFuncAttributeMaxDynamicSharedMemorySize, 90112);
        cudaFuncSetAttribute(lstm_kernel, cudaFuncAttributeNonPortableClusterSizeAllowed, 1);
        cudaFuncSetAttribute(karc,  cudaFuncAttributeMaxDynamicSharedMemorySize, 232448);
        cudaFuncSetAttribute(ksib,  cudaFuncAttributeMaxDynamicSharedMemorySize, 232448);
        cudaFuncSetAttribute(kgp,   cudaFuncAttributeMaxDynamicSharedMemorySize, 232448);
        cudaFuncSetAttribute(kgsib, cudaFuncAttributeMaxDynamicSharedMemorySize, 232448);
        attr_done = true;
    }

    prep_kernel<<<1, 256>>>(null_sib);
    zero_out_kernel<<<(NTOT + 1023) / 1024, 1024>>>(out);
    embed_kernel<<<SEQ, 128>>>(words, tags, word_emb, tag_emb);
    zin_kernel<<<dim3(50, 8), 256>>>(Wih_f, b_f, Wih_b, b_b);

    {
        cudaLaunchConfig_t cfg = {};
        cfg.gridDim  = dim3(2 * NCLUST, 1, 1);
        cfg.blockDim = dim3(256, 1, 1);
        cfg.dynamicSmemBytes = 0;
        cfg.stream = 0;
        cudaLaunchAttribute attrs[1];
        attrs[0].id = cudaLaunchAttributeClusterDimension;
        attrs[0].val.clusterDim.x = NCLUST;
        attrs[0].val.clusterDim.y = 1;
        attrs[0].val.clusterDim.z = 1;
        cfg.attrs = attrs;
        cfg.numAttrs = 1;
        (void)cudaLaunchKernelEx(&cfg, lstm_kernel, Whh_f, Whh_b);
    }

    proj_kernel<<<dim3(12, 16), 224, 86400>>>(W_proj);

    // score: blocks per chunk proportional to per-type LDS work
    karc <<<dim3(2, 4),  1024, 2 * TABSZ * 4>>>(arc_head, arc_mod, arc_head, arc_head,
                                                W_score, out, N_ARC, 0);
    ksib <<<dim3(9, 4),  1024, 3 * TABSZ * 4>>>(sib_head, sib_mod, sib_sib, sib_head,
                                                W_score, out, N_SIB, N_ARC);
    kgp  <<<dim3(9, 4),  1024, 3 * TABSZ * 4>>>(gp_head, gp_mod, gp_grand, gp_head,
                                                W_score, out, N_GP, N_ARC + N_SIB);
    kgsib<<<dim3(18, 4), 1024, 4 * TABSZ * 4>>>(gsib_head, gsib_mod, gsib_sib, gsib_grand,
                                                W_score, out, N_GSIB, N_ARC + N_SIB + N_GP);
}

// round 12
// speedup vs baseline: 2.0579x; 2.0579x over previous
#include <cuda_runtime.h>
#include <cuda_bf16.h>
#include <cstdint>

#define SEQ   256
#define XDIM  120
#define H     400
#define ZROWS 3200
#define M     200
#define TROWS 257
#define N_ARC  65536
#define N_SIB  200000
#define N_GP   200000
#define N_GSIB 300000
#define NTOT  (N_ARC + N_SIB + N_GP + N_GSIB)
#define NCLUST 16          // CTAs per direction (one cluster each)
#define UPC    25          // hidden units per CTA (400/16)
#define MC    50           // m-chunk size (4 chunks x 50 = M)
#define TABSZ (TROWS * MC)
#define SCORE_BLKX 37      // full-chip: 37 x 4 chunks = 148 blocks per score kernel

// ---------------- static device scratch (no allocations) ----------------
__device__ float g_x[SEQ * XDIM];        // embedded inputs [s][120]
__device__ float g_z[SEQ * ZROWS];       // z_in both dirs [s][dir*1600 + gate*400 + u]
__device__ float g_states[SEQ * 800];    // [s][ hf(400) | hb(400) ]
__device__ float g_ptab[12 * TROWS * M]; // 12 projection tables, row 256 = null_sib for tabs 7,10

// ---------------- helpers ----------------
__device__ __forceinline__ float fast_tanh(float x) {
    return 1.0f - 2.0f / (__expf(2.0f * x) + 1.0f);
}
__device__ __forceinline__ float tanh_ap(float x) {
    float y; asm("tanh.approx.f32 %0, %1;" : "=f"(y) : "f"(x)); return y;
}
__device__ __forceinline__ float fast_sigmoid(float x) {
    return 1.0f / (1.0f + __expf(-x));
}
__device__ __forceinline__ void cluster_sync_() {
    asm volatile("barrier.cluster.arrive.aligned;" ::: "memory");
    asm volatile("barrier.cluster.wait.aligned;" ::: "memory");
}
__device__ __forceinline__ uint32_t ctarank_() {
    uint32_t r; asm("mov.u32 %0, %%cluster_ctarank;" : "=r"(r)); return r;
}
__device__ __forceinline__ uint32_t smem_u32(const void* p) {
    uint32_t a;
    asm("{ .reg .u64 t; cvta.to.shared.u64 t, %1; cvt.u32.u64 %0, t; }" : "=r"(a) : "l"(p));
    return a;
}
__device__ __forceinline__ void st_dsmem_f32(uint32_t local_addr, uint32_t rank, float v) {
    uint32_t remote;
    asm volatile("mapa.shared::cluster.u32 %0, %1, %2;" : "=r"(remote) : "r"(local_addr), "r"(rank));
    asm volatile("st.shared::cluster.f32 [%0], %1;" :: "r"(remote), "f"(v) : "memory");
}

// ---------------- 0. prep: write null_sib rows ----------------
__global__ void prep_kernel(const float* __restrict__ null_sib) {
    int t = threadIdx.x;
    if (t < M) {
        float v = null_sib[t];
        g_ptab[(7 * TROWS + 256) * M + t]  = v;
        g_ptab[(10 * TROWS + 256) * M + t] = v;
    }
}

// ---------------- 0b. zero the output (scores accumulate via atomicAdd) ----------------
__global__ void zero_out_kernel(float* __restrict__ out) {
    int i = blockIdx.x * 1024 + threadIdx.x;
    if (i < NTOT) out[i] = 0.0f;
}

// ---------------- 1. embedding concat ----------------
__global__ void embed_kernel(const int* __restrict__ words, const int* __restrict__ tags,
                             const float* __restrict__ wemb, const float* __restrict__ temb) {
    int s = blockIdx.x, j = threadIdx.x;
    if (j < XDIM) {
        float v = (j < 100) ? wemb[words[s] * 100 + j] : temb[tags[s] * 20 + (j - 100)];
        g_x[s * XDIM + j] = v;
    }
}

// ---------------- 2. z_in = Wih @ x + b, both directions (3200 rows x 256 s) ----------------
__global__ __launch_bounds__(256) void zin_kernel(
    const float* __restrict__ Wf, const float* __restrict__ bf,
    const float* __restrict__ Wb, const float* __restrict__ bb) {
    __shared__ float Ws[64][121];
    __shared__ float Xs[32][121];
    int r0 = blockIdx.x * 64;
    int s0 = blockIdx.y * 32;
    int tid = threadIdx.x;

    for (int idx = tid; idx < 64 * 120; idx += 256) {
        int rl = idx / 120, k = idx % 120;
        int r = r0 + rl;
        Ws[rl][k] = (r < 1600) ? Wf[r * 120 + k] : Wb[(r - 1600) * 120 + k];
    }
    for (int idx = tid; idx < 32 * 120; idx += 256) {
        int sl = idx / 120, k = idx % 120;
        Xs[sl][k] = g_x[(s0 + sl) * XDIM + k];
    }
    __syncthreads();

    int tx = tid & 15;   // -> 2 sequence positions
    int ty = tid >> 4;   // -> 4 rows
    float acc[4][2] = {};
    for (int k = 0; k < 120; ++k) {
        float x0 = Xs[tx * 2 + 0][k];
        float x1 = Xs[tx * 2 + 1][k];
#pragma unroll
        for (int i = 0; i < 4; ++i) {
            float w = Ws[ty * 4 + i][k];
            acc[i][0] += w * x0;
            acc[i][1] += w * x1;
        }
    }
#pragma unroll
    for (int i = 0; i < 4; ++i) {
        int r = r0 + ty * 4 + i;
        float bias = (r < 1600) ? bf[r] : bb[r - 1600];
#pragma unroll
        for (int j = 0; j < 2; ++j) {
            int s = s0 + tx * 2 + j;
            g_z[s * ZROWS + r] = acc[i][j] + bias;
        }
    }
}

// ---------------- 3. cluster biLSTM: 2 clusters of 16 CTAs, DSMEM h-exchange ----------------
// (identical to R8's passing version: cluster.sync per step, float4 matvec)
__global__ __launch_bounds__(256, 1) void lstm_kernel(
    const float* __restrict__ Whh_f, const float* __restrict__ Whh_b) {
    const int dir  = blockIdx.x >> 4;       // blocks 0-15: fwd cluster, 16-31: bwd cluster
    const uint32_t rank = ctarank_();       // 0..15
    const int u0   = (int)rank * UPC;       // first hidden unit of this CTA
    const float* Whh = dir ? Whh_b : Whh_f;

    const int tid   = threadIdx.x;
    const int chunk = tid & 1;              // 2 col chunks of 200
    const int rl    = tid >> 1;             // 0..127 local rows; valid < 100
    const bool valid = rl < 100;
    const int gate  = valid ? (rl / UPC) : 0;
    const int lu    = valid ? (rl % UPC) : 0;
    const int grow  = gate * 400 + u0 + lu;

    // preload Whh slice: 200 cols per thread = 50 float4 = 200 regs
    float4 w[50];
    {
        const float4* wp = (const float4*)(Whh + grow * 400 + chunk * 200);
#pragma unroll
        for (int j = 0; j < 50; ++j) w[j] = wp[j];
    }

    __shared__ __align__(16) float hs[2][400];
    __shared__ float zs[100];
    float c = 0.0f;  // cell state (threads 0..24)

    // init read buffer for step 0
    for (int i = tid; i < 400; i += 256) hs[0][i] = 0.0f;
    __syncthreads();

    const uint32_t hs_base = smem_u32(&hs[0][0]);

    for (int step = 0; step < SEQ; ++step) {
        const int s = dir ? (SEQ - 1 - step) : step;
        const int p = step & 1;

        // prefetch z_in (independent of h; overlaps matvec)
        float zp0, zp1, zp2, zp3;
        if (tid < UPC) {
            const float* zin = g_z + s * ZROWS + dir * 1600 + u0 + tid;
            zp0 = __ldg(zin);
            zp1 = __ldg(zin + 400);
            zp2 = __ldg(zin + 800);
            zp3 = __ldg(zin + 1200);
        }

        // matvec: row rl (gate,lu), cols chunk*200..+200 from hs[p]
        const float4* hv = (const float4*)(&hs[p][chunk * 200]);
        float ax = 0.f, ay = 0.f, az = 0.f, aw = 0.f;
#pragma unroll
        for (int j = 0; j < 50; ++j) {
            float4 v = hv[j];
            ax += w[j].x * v.x;
            ay += w[j].y * v.y;
            az += w[j].z * v.z;
            aw += w[j].w * v.w;
        }
        float val = (ax + ay) + (az + aw);
        val += __shfl_xor_sync(0xFFFFFFFFu, val, 1);   // combine the 2 col chunks
        if (chunk == 0 && valid) zs[rl] = val;
        __syncthreads();

        if (tid < UPC) {
            float zi = zs[0 * UPC + tid] + zp0;
            float zf = zs[1 * UPC + tid] + zp1;
            float zg = zs[2 * UPC + tid] + zp2;
            float zo = zs[3 * UPC + tid] + zp3;
            float iv = fast_sigmoid(zi);
            float fv = fast_sigmoid(zf);
            float gv = fast_tanh(zg);
            float ov = fast_sigmoid(zo);
            c = fv * c + iv * gv;
            float h = ov * fast_tanh(c);
            // persist for downstream projections
            __stcg(g_states + s * 800 + dir * 400 + u0 + tid, h);
            // push into hs[p^1][u0+tid] of every CTA in the cluster (incl. self)
            uint32_t dst = hs_base + (uint32_t)((p ^ 1) * 400 + u0 + tid) * 4u;
#pragma unroll
            for (uint32_t r = 0; r < NCLUST; ++r) st_dsmem_f32(dst, r, h);
        }
        cluster_sync_();   // release our DSMEM stores, acquire peers'
    }
}

// ---------------- 4. 12 projections: ptab[p][s][m] = sum_d W_proj[p][m][d]*states[s][d] ----------------
__global__ __launch_bounds__(224) void proj_kernel(const float* __restrict__ W_proj) {
    extern __shared__ float sm[];
    float* ws = sm;            // [100 k][200 m]
    float* st = sm + 20000;    // [16 s][100 k]

    const int p   = blockIdx.x;
    const int s0  = blockIdx.y * 16;
    const int tid = threadIdx.x;

    float acc[16];
#pragma unroll
    for (int i = 0; i < 16; ++i) acc[i] = 0.0f;

    for (int dc = 0; dc < 8; ++dc) {
        __syncthreads();
        for (int idx = tid; idx < 20000; idx += 224) {
            int m = idx / 100, k = idx % 100;
            ws[k * 200 + m] = W_proj[(p * 200 + m) * 800 + dc * 100 + k];
        }
        for (int idx = tid; idx < 1600; idx += 224) {
            int sl = idx / 100, k = idx % 100;
            st[sl * 100 + k] = g_states[(s0 + sl) * 800 + dc * 100 + k];
        }
        __syncthreads();

        if (tid < 200) {
            for (int k = 0; k < 100; k += 4) {
                float w0 = ws[(k + 0) * 200 + tid];
                float w1 = ws[(k + 1) * 200 + tid];
                float w2 = ws[(k + 2) * 200 + tid];
                float w3 = ws[(k + 3) * 200 + tid];
#pragma unroll
                for (int sl = 0; sl < 16; ++sl) {
                    float4 v = *(const float4*)(st + sl * 100 + k);
                    acc[sl] += w0 * v.x + w1 * v.y + w2 * v.z + w3 * v.w;
                }
            }
        }
    }
    if (tid < 200) {
#pragma unroll
        for (int sl = 0; sl < 16; ++sl)
            g_ptab[(p * TROWS + s0 + sl) * M + tid] = acc[sl];
    }
}

// ---------------- 5. scoring: smem-resident tables, m-chunked, warp per score ----------------
// Block = (index slice via grid.x, m-chunk via grid.y) for one score type.
// All NTAB tables (257 rows x 50 m) live in smem; warp gathers rows conflict-free
// (lane = m), computes partial dot tanh(sum_rows)*W over its chunk, atomicAdds to out.
template <int NTAB, int T0, int T1, int T2, int T3, int WROW>
__global__ __launch_bounds__(1024) void score_smem_kernel(
    const int* __restrict__ i0, const int* __restrict__ i1,
    const int* __restrict__ i2, const int* __restrict__ i3,
    const float* __restrict__ W_score, float* __restrict__ out,
    int N, int out_off) {
    extern __shared__ float ts[];  // [NTAB][TROWS][MC]
    const int chunk = blockIdx.y;
    const int tid   = threadIdx.x;
    const int lane  = tid & 31;

    // load tables for this chunk
    const int tabid[4] = {T0, T1, T2, T3};
#pragma unroll
    for (int t = 0; t < NTAB; ++t) {
        const float* src = g_ptab + (size_t)tabid[t] * TROWS * M + chunk * MC;
        float* dst = ts + t * TABSZ;
        for (int idx = tid; idx < TABSZ; idx += 1024) {
            int r = idx / MC, m = idx - r * MC;
            dst[idx] = src[r * M + m];
        }
    }
    // W slice for this chunk: lane -> m=lane, m=lane+32 (valid < 50)
    float w1 = W_score[WROW * M + chunk * MC + lane];
    float w2 = (lane < MC - 32) ? W_score[WROW * M + chunk * MC + 32 + lane] : 0.0f;
    __syncthreads();

    const int warp   = (blockIdx.x * 1024 + tid) >> 5;
    const int nwarps = gridDim.x * 32;
    for (int i = warp; i < N; i += nwarps) {
        int a = __ldg(i0 + i);
        int b = __ldg(i1 + i);
        const float* r0 = ts + a * MC;
        const float* r1 = ts + TABSZ + b * MC;
        float s1 = r0[lane] + r1[lane];
        float s2 = (lane < MC - 32) ? (r0[lane + 32] + r1[lane + 32]) : 0.0f;
        if (NTAB > 2) {
            int cc = __ldg(i2 + i);
            const float* r2 = ts + 2 * TABSZ + cc * MC;
            s1 += r2[lane];
            if (lane < MC - 32) s2 += r2[lane + 32];
        }
        if (NTAB > 3) {
            int dd = __ldg(i3 + i);
            const float* r3 = ts + 3 * TABSZ + dd * MC;
            s1 += r3[lane];
            if (lane < MC - 32) s2 += r3[lane + 32];
        }
        float v = tanh_ap(s1) * w1;
        if (lane < MC - 32) v += tanh_ap(s2) * w2;
        v += __shfl_xor_sync(0xFFFFFFFFu, v, 16);
        v += __shfl_xor_sync(0xFFFFFFFFu, v, 8);
        v += __shfl_xor_sync(0xFFFFFFFFu, v, 4);
        v += __shfl_xor_sync(0xFFFFFFFFu, v, 2);
        v += __shfl_xor_sync(0xFFFFFFFFu, v, 1);
        if (lane == 0) atomicAdd(out + out_off + i, v);
    }
}

// ---------------- launch ----------------
extern "C" void kernel_launch(void* const* d_in, const int* in_sizes, int n_in,
                              void* d_out, int out_size) {
    const int*   words      = (const int*)d_in[0];
    const int*   tags       = (const int*)d_in[1];
    const int*   arc_head   = (const int*)d_in[2];
    const int*   arc_mod    = (const int*)d_in[3];
    const int*   sib_head   = (const int*)d_in[4];
    const int*   sib_mod    = (const int*)d_in[5];
    const int*   sib_sib    = (const int*)d_in[6];
    const int*   gp_head    = (const int*)d_in[7];
    const int*   gp_mod     = (const int*)d_in[8];
    const int*   gp_grand   = (const int*)d_in[9];
    const int*   gsib_head  = (const int*)d_in[10];
    const int*   gsib_mod   = (const int*)d_in[11];
    const int*   gsib_sib   = (const int*)d_in[12];
    const int*   gsib_grand = (const int*)d_in[13];
    const float* word_emb   = (const float*)d_in[14];
    const float* tag_emb    = (const float*)d_in[15];
    const float* Wih_f      = (const float*)d_in[16];
    const float* Whh_f      = (const float*)d_in[17];
    const float* b_f        = (const float*)d_in[18];
    const float* Wih_b      = (const float*)d_in[19];
    const float* Whh_b      = (const float*)d_in[20];
    const float* b_b        = (const float*)d_in[21];
    const float* W_proj     = (const float*)d_in[22];
    const float* W_score    = (const float*)d_in[23];
    const float* null_sib   = (const float*)d_in[24];
    float* out = (float*)d_out;

    // arc: tabs 0,1 | sib: 5,6,7 | gp: 3,4,2 | gsib: 8,9,10,11
    auto karc  = score_smem_kernel<2, 0, 1, 0, 0, 0>;
    auto ksib  = score_smem_kernel<3, 5, 6, 7, 0, 1>;
    auto kgp   = score_smem_kernel<3, 3, 4, 2, 0, 2>;
    auto kgsib = score_smem_kernel<4, 8, 9, 10, 11, 3>;

    static bool attr_done = false;
    if (!attr_done) {
        cudaFuncSetAttribute(proj_kernel, cudaFuncAttributeMaxDynamicSharedMemorySize, 90112);
        cudaFuncSetAttribute(lstm_kernel, cudaFuncAttributeNonPortableClusterSizeAllowed, 1);
        cudaFuncSetAttribute(karc,  cudaFuncAttributeMaxDynamicSharedMemorySize, 232448);
        cudaFuncSetAttribute(ksib,  cudaFuncAttributeMaxDynamicSharedMemorySize, 232448);
        cudaFuncSetAttribute(kgp,   cudaFuncAttributeMaxDynamicSharedMemorySize, 232448);
        cudaFuncSetAttribute(kgsib, cudaFuncAttributeMaxDynamicSharedMemorySize, 232448);
        attr_done = true;
    }

    prep_kernel<<<1, 256>>>(null_sib);
    zero_out_kernel<<<(NTOT + 1023) / 1024, 1024>>>(out);
    embed_kernel<<<SEQ, 128>>>(words, tags, word_emb, tag_emb);
    zin_kernel<<<dim3(50, 8), 256>>>(Wih_f, b_f, Wih_b, b_b);

    {
        cudaLaunchConfig_t cfg = {};
        cfg.gridDim  = dim3(2 * NCLUST, 1, 1);
        cfg.blockDim = dim3(256, 1, 1);
        cfg.dynamicSmemBytes = 0;
        cfg.stream = 0;
        cudaLaunchAttribute attrs[1];
        attrs[0].id = cudaLaunchAttributeClusterDimension;
        attrs[0].val.clusterDim.x = NCLUST;
        attrs[0].val.clusterDim.y = 1;
        attrs[0].val.clusterDim.z = 1;
        cfg.attrs = attrs;
        cfg.numAttrs = 1;
        (void)cudaLaunchKernelEx(&cfg, lstm_kernel, Whh_f, Whh_b);
    }

    proj_kernel<<<dim3(12, 16), 224, 86400>>>(W_proj);

    // score: EVERY kernel gets a full-chip grid (37 x 4 = 148 blocks = one wave);
    // the four kernels serialize on the stream, so each must fill the machine.
    karc <<<dim3(SCORE_BLKX, 4), 1024, 2 * TABSZ * 4>>>(arc_head, arc_mod, arc_head, arc_head,
                                                        W_score, out, N_ARC, 0);
    ksib <<<dim3(SCORE_BLKX, 4), 1024, 3 * TABSZ * 4>>>(sib_head, sib_mod, sib_sib, sib_head,
                                                        W_score, out, N_SIB, N_ARC);
    kgp  <<<dim3(SCORE_BLKX, 4), 1024, 3 * TABSZ * 4>>>(gp_head, gp_mod, gp_grand, gp_head,
                                                        W_score, out, N_GP, N_ARC + N_SIB);
    kgsib<<<dim3(SCORE_BLKX, 4), 1024, 4 * TABSZ * 4>>>(gsib_head, gsib_mod, gsib_sib, gsib_grand,
                                                        W_score, out, N_GSIB, N_ARC + N_SIB + N_GP);
}

// round 14
// speedup vs baseline: 2.5847x; 1.2560x over previous
#include <cuda_runtime.h>
#include <cuda_bf16.h>
#include <cstdint>

#define SEQ   256
#define XDIM  120
#define H     400
#define ZROWS 3200
#define M     200
#define TROWS 257
#define N_ARC  65536
#define N_SIB  200000
#define N_GP   200000
#define N_GSIB 300000
#define NCLUST 16          // CTAs per direction (one cluster each)
#define UPC    25          // hidden units per CTA (400/16)

// ---------------- static device scratch (no allocations) ----------------
__device__ float g_x[SEQ * XDIM];        // embedded inputs [s][120]
__device__ float g_z[SEQ * ZROWS];       // z_in both dirs [s][dir*1600 + gate*400 + u]
__device__ float g_states[SEQ * 800];    // [s][ hf(400) | hb(400) ]
__device__ float g_ptab[12 * TROWS * M]; // 12 projection tables, row 256 = null_sib for tabs 7,10

// ---------------- helpers ----------------
__device__ __forceinline__ float fast_tanh(float x) {
    return 1.0f - 2.0f / (__expf(2.0f * x) + 1.0f);
}
__device__ __forceinline__ float tanh_ap(float x) {
    float y; asm("tanh.approx.f32 %0, %1;" : "=f"(y) : "f"(x)); return y;
}
__device__ __forceinline__ float fast_sigmoid(float x) {
    return 1.0f / (1.0f + __expf(-x));
}
__device__ __forceinline__ void cluster_sync_() {
    asm volatile("barrier.cluster.arrive.aligned;" ::: "memory");
    asm volatile("barrier.cluster.wait.aligned;" ::: "memory");
}
__device__ __forceinline__ uint32_t ctarank_() {
    uint32_t r; asm("mov.u32 %0, %%cluster_ctarank;" : "=r"(r)); return r;
}
__device__ __forceinline__ uint32_t smem_u32(const void* p) {
    uint32_t a;
    asm("{ .reg .u64 t; cvta.to.shared.u64 t, %1; cvt.u32.u64 %0, t; }" : "=r"(a) : "l"(p));
    return a;
}
__device__ __forceinline__ void st_dsmem_f32(uint32_t local_addr, uint32_t rank, float v) {
    uint32_t remote;
    asm volatile("mapa.shared::cluster.u32 %0, %1, %2;" : "=r"(remote) : "r"(local_addr), "r"(rank));
    asm volatile("st.shared::cluster.f32 [%0], %1;" :: "r"(remote), "f"(v) : "memory");
}
// packed f32x2 helpers (Blackwell; FFMA2 is PTX-only)
__device__ __forceinline__ unsigned long long pk2(float x, float y) {
    unsigned long long r; asm("mov.b64 %0, {%1, %2};" : "=l"(r) : "f"(x), "f"(y)); return r;
}
__device__ __forceinline__ void upk2(unsigned long long v, float& x, float& y) {
    asm("mov.b64 {%0, %1}, %2;" : "=f"(x), "=f"(y) : "l"(v));
}
__device__ __forceinline__ unsigned long long fma2(unsigned long long a, unsigned long long b,
                                                   unsigned long long c) {
    unsigned long long d;
    asm("fma.rn.f32x2 %0, %1, %2, %3;" : "=l"(d) : "l"(a), "l"(b), "l"(c));
    return d;
}

// ---------------- 0. prep: write null_sib rows ----------------
__global__ void prep_kernel(const float* __restrict__ null_sib) {
    int t = threadIdx.x;
    if (t < M) {
        float v = null_sib[t];
        g_ptab[(7 * TROWS + 256) * M + t]  = v;
        g_ptab[(10 * TROWS + 256) * M + t] = v;
    }
}

// ---------------- 1. embedding concat ----------------
__global__ void embed_kernel(const int* __restrict__ words, const int* __restrict__ tags,
                             const float* __restrict__ wemb, const float* __restrict__ temb) {
    int s = blockIdx.x, j = threadIdx.x;
    if (j < XDIM) {
        float v = (j < 100) ? wemb[words[s] * 100 + j] : temb[tags[s] * 20 + (j - 100)];
        g_x[s * XDIM + j] = v;
    }
}

// ---------------- 2. z_in = Wih @ x + b, both directions (3200 rows x 256 s) ----------------
__global__ __launch_bounds__(256) void zin_kernel(
    const float* __restrict__ Wf, const float* __restrict__ bf,
    const float* __restrict__ Wb, const float* __restrict__ bb) {
    __shared__ float Ws[64][121];
    __shared__ float Xs[32][121];
    int r0 = blockIdx.x * 64;
    int s0 = blockIdx.y * 32;
    int tid = threadIdx.x;

    for (int idx = tid; idx < 64 * 120; idx += 256) {
        int rl = idx / 120, k = idx % 120;
        int r = r0 + rl;
        Ws[rl][k] = (r < 1600) ? Wf[r * 120 + k] : Wb[(r - 1600) * 120 + k];
    }
    for (int idx = tid; idx < 32 * 120; idx += 256) {
        int sl = idx / 120, k = idx % 120;
        Xs[sl][k] = g_x[(s0 + sl) * XDIM + k];
    }
    __syncthreads();

    int tx = tid & 15;   // -> 2 sequence positions
    int ty = tid >> 4;   // -> 4 rows
    float acc[4][2] = {};
    for (int k = 0; k < 120; ++k) {
        float x0 = Xs[tx * 2 + 0][k];
        float x1 = Xs[tx * 2 + 1][k];
#pragma unroll
        for (int i = 0; i < 4; ++i) {
            float w = Ws[ty * 4 + i][k];
            acc[i][0] += w * x0;
            acc[i][1] += w * x1;
        }
    }
#pragma unroll
    for (int i = 0; i < 4; ++i) {
        int r = r0 + ty * 4 + i;
        float bias = (r < 1600) ? bf[r] : bb[r - 1600];
#pragma unroll
        for (int j = 0; j < 2; ++j) {
            int s = s0 + tx * 2 + j;
            g_z[s * ZROWS + r] = acc[i][j] + bias;
        }
    }
}

// ---------------- 3. cluster biLSTM: 2 clusters of 16 CTAs, DSMEM h-exchange ----------------
// R8 structure (cluster.sync per step); R13 change: matvec packed as fma.rn.f32x2.
__global__ __launch_bounds__(256, 1) void lstm_kernel(
    const float* __restrict__ Whh_f, const float* __restrict__ Whh_b) {
    const int dir  = blockIdx.x >> 4;       // blocks 0-15: fwd cluster, 16-31: bwd cluster
    const uint32_t rank = ctarank_();       // 0..15
    const int u0   = (int)rank * UPC;       // first hidden unit of this CTA
    const float* Whh = dir ? Whh_b : Whh_f;

    const int tid   = threadIdx.x;
    const int chunk = tid & 1;              // 2 col chunks of 200
    const int rl    = tid >> 1;             // 0..127 local rows; valid < 100
    const bool valid = rl < 100;
    const int gate  = valid ? (rl / UPC) : 0;
    const int lu    = valid ? (rl % UPC) : 0;
    const int grow  = gate * 400 + u0 + lu;

    // preload Whh slice packed f32x2: 200 cols per thread = 100 x 64-bit = 200 regs
    unsigned long long w01[50], w23[50];
    {
        const float4* wp = (const float4*)(Whh + grow * 400 + chunk * 200);
#pragma unroll
        for (int j = 0; j < 50; ++j) {
            float4 t = wp[j];
            w01[j] = pk2(t.x, t.y);
            w23[j] = pk2(t.z, t.w);
        }
    }

    __shared__ __align__(16) float hs[2][400];
    __shared__ float zs[100];
    float c = 0.0f;  // cell state (threads 0..24)

    // init read buffer for step 0
    for (int i = tid; i < 400; i += 256) hs[0][i] = 0.0f;
    __syncthreads();

    const uint32_t hs_base = smem_u32(&hs[0][0]);

    for (int step = 0; step < SEQ; ++step) {
        const int s = dir ? (SEQ - 1 - step) : step;
        const int p = step & 1;

        // prefetch z_in (independent of h; overlaps matvec)
        float zp0, zp1, zp2, zp3;
        if (tid < UPC) {
            const float* zin = g_z + s * ZROWS + dir * 1600 + u0 + tid;
            zp0 = __ldg(zin);
            zp1 = __ldg(zin + 400);
            zp2 = __ldg(zin + 800);
            zp3 = __ldg(zin + 1200);
        }

        // matvec: row rl (gate,lu), cols chunk*200..+200 from hs[p], packed f32x2
        const float4* hv = (const float4*)(&hs[p][chunk * 200]);
        unsigned long long a01 = 0ull, a23 = 0ull;
#pragma unroll
        for (int j = 0; j < 50; ++j) {
            float4 v = hv[j];
            a01 = fma2(w01[j], pk2(v.x, v.y), a01);
            a23 = fma2(w23[j], pk2(v.z, v.w), a23);
        }
        float ax, ay, az, aw;
        upk2(a01, ax, ay);
        upk2(a23, az, aw);
        float val = (ax + ay) + (az + aw);
        val += __shfl_xor_sync(0xFFFFFFFFu, val, 1);   // combine the 2 col chunks
        if (chunk == 0 && valid) zs[rl] = val;
        __syncthreads();

        if (tid < UPC) {
            float zi = zs[0 * UPC + tid] + zp0;
            float zf = zs[1 * UPC + tid] + zp1;
            float zg = zs[2 * UPC + tid] + zp2;
            float zo = zs[3 * UPC + tid] + zp3;
            float iv = fast_sigmoid(zi);
            float fv = fast_sigmoid(zf);
            float gv = fast_tanh(zg);
            float ov = fast_sigmoid(zo);
            c = fv * c + iv * gv;
            float h = ov * fast_tanh(c);
            // persist for downstream projections
            __stcg(g_states + s * 800 + dir * 400 + u0 + tid, h);
            // push into hs[p^1][u0+tid] of every CTA in the cluster (incl. self)
            uint32_t dst = hs_base + (uint32_t)((p ^ 1) * 400 + u0 + tid) * 4u;
#pragma unroll
            for (uint32_t r = 0; r < NCLUST; ++r) st_dsmem_f32(dst, r, h);
        }
        cluster_sync_();   // release our DSMEM stores, acquire peers'
    }
}

// ---------------- 4. 12 projections: ptab[p][s][m] = sum_d W_proj[p][m][d]*states[s][d] ----------------
__global__ __launch_bounds__(224) void proj_kernel(const float* __restrict__ W_proj) {
    extern __shared__ float sm[];
    float* ws = sm;            // [100 k][200 m]
    float* st = sm + 20000;    // [16 s][100 k]

    const int p   = blockIdx.x;
    const int s0  = blockIdx.y * 16;
    const int tid = threadIdx.x;

    float acc[16];
#pragma unroll
    for (int i = 0; i < 16; ++i) acc[i] = 0.0f;

    for (int dc = 0; dc < 8; ++dc) {
        __syncthreads();
        for (int idx = tid; idx < 20000; idx += 224) {
            int m = idx / 100, k = idx % 100;
            ws[k * 200 + m] = W_proj[(p * 200 + m) * 800 + dc * 100 + k];
        }
        for (int idx = tid; idx < 1600; idx += 224) {
            int sl = idx / 100, k = idx % 100;
            st[sl * 100 + k] = g_states[(s0 + sl) * 800 + dc * 100 + k];
        }
        __syncthreads();

        if (tid < 200) {
            for (int k = 0; k < 100; k += 4) {
                float w0 = ws[(k + 0) * 200 + tid];
                float w1 = ws[(k + 1) * 200 + tid];
                float w2 = ws[(k + 2) * 200 + tid];
                float w3 = ws[(k + 3) * 200 + tid];
#pragma unroll
                for (int sl = 0; sl < 16; ++sl) {
                    float4 v = *(const float4*)(st + sl * 100 + k);
                    acc[sl] += w0 * v.x + w1 * v.y + w2 * v.z + w3 * v.w;
                }
            }
        }
    }
    if (tid < 200) {
#pragma unroll
        for (int sl = 0; sl < 16; ++sl)
            g_ptab[(p * TROWS + s0 + sl) * M + tid] = acc[sl];
    }
}

// ---------------- 5. scoring: warp per score (4 scores / warp; R8 version) ----------------
template <int NR>
__device__ __forceinline__ float warp_score(const float* __restrict__ wsrow,
                                            const float* r0, const float* r1,
                                            const float* r2, const float* r3, int lane) {
    float acc = 0.0f;
#pragma unroll
    for (int it = 0; it < 4; ++it) {
        int m2 = it * 32 + lane;  // float2 index, valid < 100
        if (m2 < 100) {
            float2 a = ((const float2*)r0)[m2];
            float2 b = ((const float2*)r1)[m2];
            float sx = a.x + b.x, sy = a.y + b.y;
            if (NR > 2) {
                float2 cc = ((const float2*)r2)[m2];
                sx += cc.x; sy += cc.y;
            }
            if (NR > 3) {
                float2 d = ((const float2*)r3)[m2];
                sx += d.x; sy += d.y;
            }
            float2 w = ((const float2*)wsrow)[m2];
            acc += tanh_ap(sx) * w.x + tanh_ap(sy) * w.y;
        }
    }
    acc += __shfl_xor_sync(0xFFFFFFFFu, acc, 16);
    acc += __shfl_xor_sync(0xFFFFFFFFu, acc, 8);
    acc += __shfl_xor_sync(0xFFFFFFFFu, acc, 4);
    acc += __shfl_xor_sync(0xFFFFFFFFu, acc, 2);
    acc += __shfl_xor_sync(0xFFFFFFFFu, acc, 1);
    return acc;
}

#define GA (N_ARC / 4)
#define GS (N_SIB / 4)
#define GG (N_GP / 4)
#define GX (N_GSIB / 4)
#define TOTAL_GROUPS (GA + GS + GG + GX)

__global__ __launch_bounds__(256) void score_kernel(
    const int* __restrict__ arc_head, const int* __restrict__ arc_mod,
    const int* __restrict__ sib_head, const int* __restrict__ sib_mod, const int* __restrict__ sib_sib,
    const int* __restrict__ gp_head,  const int* __restrict__ gp_mod,  const int* __restrict__ gp_grand,
    const int* __restrict__ gsib_head, const int* __restrict__ gsib_mod,
    const int* __restrict__ gsib_sib,  const int* __restrict__ gsib_grand,
    const float* __restrict__ W_score, float* __restrict__ out) {
    int gw   = (blockIdx.x * blockDim.x + threadIdx.x) >> 5;
    int lane = threadIdx.x & 31;
    if (gw >= TOTAL_GROUPS) return;

    const float* tab = g_ptab;
    const float* t0 = tab + 0  * TROWS * M;
    const float* t1 = tab + 1  * TROWS * M;
    const float* t2 = tab + 2  * TROWS * M;
    const float* t3 = tab + 3  * TROWS * M;
    const float* t4 = tab + 4  * TROWS * M;
    const float* t5 = tab + 5  * TROWS * M;
    const float* t6 = tab + 6  * TROWS * M;
    const float* t7 = tab + 7  * TROWS * M;
    const float* t8 = tab + 8  * TROWS * M;
    const float* t9 = tab + 9  * TROWS * M;
    const float* t10 = tab + 10 * TROWS * M;
    const float* t11 = tab + 11 * TROWS * M;

    if (gw < GA) {
        int base = gw * 4;
#pragma unroll
        for (int k = 0; k < 4; ++k) {
            int i = base + k;
            float sc = warp_score<2>(W_score + 0 * M,
                                     t0 + arc_head[i] * M, t1 + arc_mod[i] * M,
                                     t0, t0, lane);
            if (lane == 0) out[i] = sc;
        }
    } else if (gw < GA + GS) {
        int base = (gw - GA) * 4;
#pragma unroll
        for (int k = 0; k < 4; ++k) {
            int i = base + k;
            float sc = warp_score<3>(W_score + 1 * M,
                                     t5 + sib_head[i] * M, t6 + sib_mod[i] * M,
                                     t7 + sib_sib[i] * M, t0, lane);
            if (lane == 0) out[N_ARC + i] = sc;
        }
    } else if (gw < GA + GS + GG) {
        int base = (gw - GA - GS) * 4;
#pragma unroll
        for (int k = 0; k < 4; ++k) {
            int i = base + k;
            float sc = warp_score<3>(W_score + 2 * M,
                                     t3 + gp_head[i] * M, t4 + gp_mod[i] * M,
                                     t2 + gp_grand[i] * M, t0, lane);
            if (lane == 0) out[N_ARC + N_SIB + i] = sc;
        }
    } else {
        int base = (gw - GA - GS - GG) * 4;
#pragma unroll
        for (int k = 0; k < 4; ++k) {
            int i = base + k;
            float sc = warp_score<4>(W_score + 3 * M,
                                     t8 + gsib_head[i] * M, t9 + gsib_mod[i] * M,
                                     t10 + gsib_sib[i] * M, t11 + gsib_grand[i] * M, lane);
            if (lane == 0) out[N_ARC + N_SIB + N_GP + i] = sc;
        }
    }
}

// ---------------- launch ----------------
extern "C" void kernel_launch(void* const* d_in, const int* in_sizes, int n_in,
                              void* d_out, int out_size) {
    const int*   words      = (const int*)d_in[0];
    const int*   tags       = (const int*)d_in[1];
    const int*   arc_head   = (const int*)d_in[2];
    const int*   arc_mod    = (const int*)d_in[3];
    const int*   sib_head   = (const int*)d_in[4];
    const int*   sib_mod    = (const int*)d_in[5];
    const int*   sib_sib    = (const int*)d_in[6];
    const int*   gp_head    = (const int*)d_in[7];
    const int*   gp_mod     = (const int*)d_in[8];
    const int*   gp_grand   = (const int*)d_in[9];
    const int*   gsib_head  = (const int*)d_in[10];
    const int*   gsib_mod   = (const int*)d_in[11];
    const int*   gsib_sib   = (const int*)d_in[12];
    const int*   gsib_grand = (const int*)d_in[13];
    const float* word_emb   = (const float*)d_in[14];
    const float* tag_emb    = (const float*)d_in[15];
    const float* Wih_f      = (const float*)d_in[16];
    const float* Whh_f      = (const float*)d_in[17];
    const float* b_f        = (const float*)d_in[18];
    const float* Wih_b      = (const float*)d_in[19];
    const float* Whh_b      = (const float*)d_in[20];
    const float* b_b        = (const float*)d_in[21];
    const float* W_proj     = (const float*)d_in[22];
    const float* W_score    = (const float*)d_in[23];
    const float* null_sib   = (const float*)d_in[24];
    float* out = (float*)d_out;

    static bool attr_done = false;
    if (!attr_done) {
        cudaFuncSetAttribute(proj_kernel, cudaFuncAttributeMaxDynamicSharedMemorySize, 90112);
        cudaFuncSetAttribute(lstm_kernel, cudaFuncAttributeNonPortableClusterSizeAllowed, 1);
        attr_done = true;
    }

    prep_kernel<<<1, 256>>>(null_sib);
    embed_kernel<<<SEQ, 128>>>(words, tags, word_emb, tag_emb);
    zin_kernel<<<dim3(50, 8), 256>>>(Wih_f, b_f, Wih_b, b_b);

    {
        cudaLaunchConfig_t cfg = {};
        cfg.gridDim  = dim3(2 * NCLUST, 1, 1);
        cfg.blockDim = dim3(256, 1, 1);
        cfg.dynamicSmemBytes = 0;
        cfg.stream = 0;
        cudaLaunchAttribute attrs[1];
        attrs[0].id = cudaLaunchAttributeClusterDimension;
        attrs[0].val.clusterDim.x = NCLUST;
        attrs[0].val.clusterDim.y = 1;
        attrs[0].val.clusterDim.z = 1;
        cfg.attrs = attrs;
        cfg.numAttrs = 1;
        (void)cudaLaunchKernelEx(&cfg, lstm_kernel, Whh_f, Whh_b);
    }

    proj_kernel<<<dim3(12, 16), 224, 86400>>>(W_proj);
    score_kernel<<<(TOTAL_GROUPS + 7) / 8, 256>>>(
        arc_head, arc_mod, sib_head, sib_mod, sib_sib,
        gp_head, gp_mod, gp_grand,
        gsib_head, gsib_mod, gsib_sib, gsib_grand,
        W_score, out);
}